// round 14
// baseline (speedup 1.0000x reference)
#include <cuda_runtime.h>
#include <cuda_fp16.h>
#include <math.h>
#include <stdint.h>

#define RDIM 256
#define SDIM 1024
#define CDIM 256
#define NTA  8          // 128-token tiles per row (kernel A)

typedef unsigned long long ull;

// ---------------- device scratch ----------------
__device__ __half g_kvh[(size_t)RDIM*SDIM*64]; // per token: [0:32)=k, [32:64)=v (fp16)
__device__ float  g_qpool_part[RDIM*NTA*CDIM];
__device__ float  g_msum_part[RDIM*NTA];
__device__ float  g_gate[RDIM*CDIM];           // attention output o[r, h*32+c]
__device__ float  g_WkvT[64*CDIM];             // [Wk|Wv] transposed [n][k], tf32 RNA
__device__ __half g_WgTh[CDIM*CDIM];           // Wg transposed [n][k], fp16
__device__ __half g_WoTh[CDIM*CDIM];           // Wo transposed [n][k], fp16
__device__ __half g_mh[(size_t)RDIM*SDIM*CDIM];// fp16 copy of m (written by kA)

// ---------------- helpers ----------------
__device__ __forceinline__ uint32_t s2u(const void* p){
  uint32_t a;
  asm("{ .reg .u64 t; cvta.to.shared.u64 t, %1; cvt.u32.u64 %0, t; }" : "=r"(a) : "l"(p));
  return a;
}
__device__ __forceinline__ uint32_t tf32r(float x){
  uint32_t u; asm("cvt.rna.tf32.f32 %0, %1;" : "=r"(u) : "f"(x)); return u;
}
__device__ __forceinline__ void cpa16(uint32_t dst, const void* src){
  asm volatile("cp.async.cg.shared.global [%0], [%1], 16;" :: "r"(dst), "l"(src));
}
#define CP_COMMIT() asm volatile("cp.async.commit_group;" ::: "memory")
#define CP_WAIT0()  asm volatile("cp.async.wait_group 0;" ::: "memory")

__device__ __forceinline__ void mma8(float d[4], const uint32_t a[4], const uint32_t b[2]){
  asm volatile(
    "mma.sync.aligned.m16n8k8.row.col.f32.tf32.tf32.f32 "
    "{%0,%1,%2,%3}, {%4,%5,%6,%7}, {%8,%9}, {%0,%1,%2,%3};"
    : "+f"(d[0]), "+f"(d[1]), "+f"(d[2]), "+f"(d[3])
    : "r"(a[0]), "r"(a[1]), "r"(a[2]), "r"(a[3]), "r"(b[0]), "r"(b[1]));
}
__device__ __forceinline__ void mma16h(float d[4], const uint32_t a[4], const uint32_t b[2]){
  asm volatile(
    "mma.sync.aligned.m16n8k16.row.col.f32.f16.f16.f32 "
    "{%0,%1,%2,%3}, {%4,%5,%6,%7}, {%8,%9}, {%0,%1,%2,%3};"
    : "+f"(d[0]), "+f"(d[1]), "+f"(d[2]), "+f"(d[3])
    : "r"(a[0]), "r"(a[1]), "r"(a[2]), "r"(a[3]), "r"(b[0]), "r"(b[1]));
}
__device__ __forceinline__ void ldsm4(uint32_t &r0, uint32_t &r1, uint32_t &r2, uint32_t &r3,
                                      uint32_t addr){
  asm volatile("ldmatrix.sync.aligned.m8n8.x4.shared.b16 {%0,%1,%2,%3}, [%4];"
    : "=r"(r0), "=r"(r1), "=r"(r2), "=r"(r3) : "r"(addr));
}

// ---------------- Kernel P: transpose + round weights ----------------
__global__ void __launch_bounds__(256) kprep(const float* __restrict__ Wg,
                                             const float* __restrict__ Wo,
                                             const float* __restrict__ Wk,
                                             const float* __restrict__ Wv)
{
  const int n = blockIdx.x, k = threadIdx.x;
  g_WgTh[n*CDIM + k] = __float2half(Wg[k*CDIM + n]);
  g_WoTh[n*CDIM + k] = __float2half(Wo[k*CDIM + n]);
  if (n < 32)       g_WkvT[n*CDIM + k] = __uint_as_float(tf32r(Wk[k*32 + n]));
  else if (n < 64)  g_WkvT[n*CDIM + k] = __uint_as_float(tf32r(Wv[k*32 + (n-32)]));
}

// ---------------- Kernel A: k/v projection (tf32 mma + ldmatrix) + qpool + m->fp16 ----------------
#define KA_ALD   36
#define KA_ASZ   (128*KA_ALD)
#define KA_BOFF  (2*KA_ASZ)
#define KA_BLD   260
#define KA_MSK   (KA_BOFF + 64*KA_BLD)
#define KA_SMEM  ((KA_MSK + 128)*4)    // 103936 B

union H2U4 { uint4 v; __half2 h[4]; };

__global__ void __launch_bounds__(256,2) ka_kv(const float* __restrict__ m,
                                               const float* __restrict__ mask)
{
  extern __shared__ float sm[];
  const uint32_t sbu = s2u(sm);
  const int t = threadIdx.x, lane = t&31, w = t>>5;
  const int wm = w>>1, wn = w&1;
  const int lq = lane>>2, lr = lane&3;
  const int til = lane>>3, rw = lane&7;
  const int r = blockIdx.y, tile = blockIdx.x, s0 = tile*128;

  const float4* m4 = (const float4*)(m + (size_t)(r*SDIM + s0)*CDIM);
  const float4* B4 = (const float4*)g_WkvT;

  const uint32_t offA36  = (uint32_t)((((til&1)*8 + rw)*KA_ALD)*4 + (til>>1)*16);
  const uint32_t offB260 = (uint32_t)((((til>>1)*8 + rw)*KA_BLD)*4 + (til&1)*16);

  if (t < 128) sm[KA_MSK + t] = mask[r*SDIM + s0 + t];

  #pragma unroll
  for (int i=0;i<16;i++){
    int f = i*256 + t; int n = f>>6, q = f&63;
    cpa16(sbu + (uint32_t)(KA_BOFF + n*KA_BLD + q*4)*4, B4 + n*64 + q);
  }
  #pragma unroll
  for (int i=0;i<4;i++){
    int f = i*256 + t; int row = f>>3, q = f&7;
    cpa16(sbu + (uint32_t)(0*KA_ASZ + row*KA_ALD + q*4)*4, m4 + row*64 + 0*8 + q);
  }
  CP_COMMIT(); CP_WAIT0();
  __syncthreads();

  if (t < 32){
    float s = sm[KA_MSK+t] + sm[KA_MSK+t+32] + sm[KA_MSK+t+64] + sm[KA_MSK+t+96];
    #pragma unroll
    for (int o=16;o;o>>=1) s += __shfl_xor_sync(0xffffffffu, s, o);
    if (t==0) g_msum_part[r*NTA + tile] = s;
  }

  float acc[2][4][4];
  #pragma unroll
  for (int mi=0;mi<2;mi++)
    #pragma unroll
    for (int ni=0;ni<4;ni++)
      #pragma unroll
      for (int q=0;q<4;q++) acc[mi][ni][q]=0.f;

  const int qch = t>>3, qsub = t&7;

  for (int kc=0;kc<8;kc++){
    if (kc<7){
      #pragma unroll
      for (int i=0;i<4;i++){
        int f = i*256 + t; int row = f>>3, q = f&7;
        cpa16(sbu + (uint32_t)(((kc+1)&1)*KA_ASZ + row*KA_ALD + q*4)*4,
              m4 + row*64 + (kc+1)*8 + q);
      }
      CP_COMMIT();
    }
    const float* As = sm + (kc&1)*KA_ASZ;
    const uint32_t aBase = sbu + (uint32_t)(((kc&1)*KA_ASZ + wm*32*KA_ALD)*4) + offA36;
    const uint32_t bBase = sbu + (uint32_t)((KA_BOFF + wn*32*KA_BLD + kc*32)*4) + offB260;
    #pragma unroll
    for (int s=0;s<4;s++){
      uint32_t a[2][4], b[4][2];
      ldsm4(a[0][0],a[0][1],a[0][2],a[0][3], aBase + s*32);
      ldsm4(a[1][0],a[1][1],a[1][2],a[1][3], aBase + (uint32_t)(16*KA_ALD*4) + s*32);
      ldsm4(b[0][0],b[0][1],b[1][0],b[1][1], bBase + s*32);
      ldsm4(b[2][0],b[2][1],b[3][0],b[3][1], bBase + (uint32_t)(16*KA_BLD*4) + s*32);
      #pragma unroll
      for (int mi=0;mi<2;mi++)
        #pragma unroll
        for (int ni=0;ni<4;ni++)
          mma8(acc[mi][ni], a[mi], b[ni]);
    }
    // fused qpool partial (exact fp32)
    {
      float qa = 0.f;
      #pragma unroll
      for (int j=0;j<16;j++){
        int row = qsub + 8*j;
        qa += As[row*KA_ALD + qch] * sm[KA_MSK + row];
      }
      qa += __shfl_xor_sync(0xffffffffu, qa, 4);
      qa += __shfl_xor_sync(0xffffffffu, qa, 2);
      qa += __shfl_xor_sync(0xffffffffu, qa, 1);
      if (qsub==0) g_qpool_part[(r*NTA + tile)*CDIM + kc*32 + qch] = qa;
    }
    // fp16 m copy
    {
      int row = t>>1, seg = t&1;
      const float* src = As + row*KA_ALD + seg*16;
      H2U4 u0, u1;
      #pragma unroll
      for (int j=0;j<4;j++) u0.h[j] = __floats2half2_rn(src[2*j],   src[2*j+1]);
      #pragma unroll
      for (int j=0;j<4;j++) u1.h[j] = __floats2half2_rn(src[8+2*j], src[8+2*j+1]);
      __half* dst = g_mh + (size_t)(r*SDIM + s0 + row)*CDIM + kc*32 + seg*16;
      *(uint4*)dst       = u0.v;
      *((uint4*)dst + 1) = u1.v;
    }
    if (kc<7) CP_WAIT0();
    __syncthreads();
  }

  // store k/v (fp16)
  #pragma unroll
  for (int mi=0;mi<2;mi++){
    #pragma unroll
    for (int ni=0;ni<4;ni++){
      const int col0 = wn*32 + ni*8 + lr*2;
      const int row0 = wm*32 + mi*16 + lq;
      *(__half2*)(g_kvh + (size_t)(r*SDIM + s0 + row0)*64 + col0) =
          __floats2half2_rn(acc[mi][ni][0], acc[mi][ni][1]);
      *(__half2*)(g_kvh + (size_t)(r*SDIM + s0 + row0+8)*64 + col0) =
          __floats2half2_rn(acc[mi][ni][2], acc[mi][ni][3]);
    }
  }
}

// ---------------- Kernel B: q, logits, softmax, o (fp32 math, fp16 k/v) ----------------
__global__ void __launch_bounds__(256) kb_attn(const float* __restrict__ mask,
                                               const float* __restrict__ Wq)
{
  __shared__ float qp[256];
  __shared__ float qh[256];
  __shared__ float lg[8*1024];
  __shared__ float vs[128*36];
  __shared__ float msum_s;
  const int t = threadIdx.x, r = blockIdx.x;

  float qa = 0.f;
  #pragma unroll
  for (int i=0;i<NTA;i++) qa += g_qpool_part[(r*NTA+i)*CDIM + t];
  if (t==0){
    float s=0.f;
    #pragma unroll
    for (int i=0;i<NTA;i++) s += g_msum_part[r*NTA+i];
    msum_s = s;
  }
  __syncthreads();
  qp[t] = qa / (msum_s + 1e-10f);
  __syncthreads();

  float qv = 0.f;
  for (int c=0;c<CDIM;c++) qv += qp[c]*Wq[c*256+t];
  qh[t] = qv * 0.17677669529663687f;
  __syncthreads();

  for (int it=0; it<4; it++){
    int s = it*256 + t;
    float kreg[32];
    const uint4* kv = (const uint4*)(g_kvh + (size_t)(r*SDIM+s)*64);
    #pragma unroll
    for (int qq=0;qq<4;qq++){
      H2U4 u; u.v = kv[qq];
      #pragma unroll
      for (int j=0;j<4;j++){
        float2 f2 = __half22float2(u.h[j]);
        kreg[qq*8+2*j]   = f2.x;
        kreg[qq*8+2*j+1] = f2.y;
      }
    }
    float bias = 1.0e9f*(mask[r*SDIM+s]-1.0f);
    #pragma unroll
    for (int h=0;h<8;h++){
      float d=0.f;
      #pragma unroll
      for (int q=0;q<32;q++) d += qh[h*32+q]*kreg[q];
      lg[h*1024+s] = d + bias;
    }
  }
  __syncthreads();

  const int w = t>>5, lane = t&31;
  {
    float mx = -3.4e38f;
    for (int s=lane; s<1024; s+=32) mx = fmaxf(mx, lg[w*1024+s]);
    #pragma unroll
    for (int o=16;o;o>>=1) mx = fmaxf(mx, __shfl_xor_sync(0xffffffffu, mx, o));
    float sum = 0.f;
    for (int s=lane; s<1024; s+=32){
      float e = __expf(lg[w*1024+s]-mx);
      lg[w*1024+s] = e; sum += e;
    }
    #pragma unroll
    for (int o=16;o;o>>=1) sum += __shfl_xor_sync(0xffffffffu, sum, o);
    float inv = 1.0f/sum;
    for (int s=lane; s<1024; s+=32) lg[w*1024+s] *= inv;
  }
  __syncthreads();

  float acc = 0.f;
  for (int tile=0;tile<8;tile++){
    {
      int tk = t>>1, seg = t&1;
      const uint4* src = (const uint4*)(g_kvh + (size_t)(r*SDIM+tile*128+tk)*64 + 32 + seg*16);
      H2U4 u0, u1; u0.v = src[0]; u1.v = src[1];
      float* d = vs + tk*36 + seg*16;
      #pragma unroll
      for (int j=0;j<4;j++){
        float2 f2 = __half22float2(u0.h[j]);
        d[2*j] = f2.x; d[2*j+1] = f2.y;
      }
      #pragma unroll
      for (int j=0;j<4;j++){
        float2 f2 = __half22float2(u1.h[j]);
        d[8+2*j] = f2.x; d[8+2*j+1] = f2.y;
      }
    }
    __syncthreads();
    #pragma unroll 8
    for (int tk=0;tk<128;tk++) acc += lg[w*1024 + tile*128+tk] * vs[tk*36 + lane];
    __syncthreads();
  }
  g_gate[r*CDIM + t] = acc;
}

// ---------------- Kernel C: out = (sigmoid(m@Wg+bg)*o) @ Wo + bo  (fp16 mma, pipelined frags) ----------------
// CTA tile 64 tokens x 256 n; 256 threads = 8 warps (2x4), warp tile 32x64.
// K chunks of 64; A+B double-buffered; T fp16 resident. 1 CTA/SM -> up to 255 regs
// so fragments are double-buffered across s-steps (LDSM of s+1 overlaps HMMA of s).
#define KCM     64
#define A_LDB   144                   // A chunk row stride bytes (64 halves + 16B pad)
#define A_SZB   (KCM*A_LDB)           // 9216
#define B_LDB   144
#define B_SZB   (256*B_LDB)           // 36864
#define AOFF(b) ((b)*A_SZB)
#define BOFF(b) (2*A_SZB + (b)*B_SZB)
#define T_OFF   (2*A_SZB + 2*B_SZB)   // 92160
#define T_LDB   528                   // 256 halves + pad (bytes)
#define OGB     (T_OFF + KCM*T_LDB)   // 125952
#define BGB     (OGB + 1024)
#define BOB     (BGB + 1024)
#define KC_SMEM_BYTES (BOB + 1024)    // 129024

__global__ void __launch_bounds__(256,1) kc_mma(const float* __restrict__ bgp,
    const float* __restrict__ bop, float* __restrict__ out)
{
  extern __shared__ char smc[];
  const uint32_t sbu = s2u(smc);
  float* ogf = (float*)(smc + OGB);
  float* bgf = (float*)(smc + BGB);
  float* bof = (float*)(smc + BOB);
  const int t = threadIdx.x, lane = t&31, w = t>>5;
  const int wm = w>>2, wn = w&3;           // 2(m) x 4(n) warp grid
  const int lq = lane>>2, lr = lane&3;
  const int til = lane>>3, rw = lane&7;
  const int r = blockIdx.y, tile = blockIdx.x, s0 = tile*KCM;

  ogf[t] = g_gate[r*CDIM+t];
  bgf[t] = bgp[t];
  bof[t] = bop[t];

  const __half* mh = g_mh + (size_t)(r*SDIM + s0)*CDIM;

  const uint32_t offA144 = (uint32_t)(((til&1)*8 + rw)*A_LDB + (til>>1)*16);
  const uint32_t offA528 = (uint32_t)(((til&1)*8 + rw)*T_LDB + (til>>1)*16);
  const uint32_t offB144 = (uint32_t)(((til>>1)*8 + rw)*B_LDB + (til&1)*16);

  float acc[2][8][4];
  #pragma unroll
  for (int mi=0;mi<2;mi++)
    #pragma unroll
    for (int ni=0;ni<8;ni++)
      #pragma unroll
      for (int q=0;q<4;q++) acc[mi][ni][q]=0.f;

  // A chunk: 64 rows x 64 halves = 512 x 16B, 2 per thread
  #define LOAD_A64(kc, b) do { \
    _Pragma("unroll") \
    for (int i=0;i<2;i++){ \
      int f=i*256+t; int row=f>>3, q=f&7; \
      cpa16(sbu + (uint32_t)(AOFF(b) + row*A_LDB + q*16), \
            mh + (size_t)row*CDIM + (kc)*64 + q*8); \
    } } while(0)
  // B chunk: 256 n x 64 halves = 2048 x 16B, 8 per thread
  #define LOAD_B64(Wh, kc, b) do { \
    _Pragma("unroll") \
    for (int i=0;i<8;i++){ \
      int f=i*256+t; int n=f>>3, q=f&7; \
      cpa16(sbu + (uint32_t)(BOFF(b) + n*B_LDB + q*16), \
            (Wh) + (size_t)n*CDIM + (kc)*64 + q*8); \
    } } while(0)

  #define LDFRAG(P, aBase, bBase, LDAB, s) do { \
    ldsm4(af[P][0][0],af[P][0][1],af[P][0][2],af[P][0][3], (aBase) + (s)*32); \
    ldsm4(af[P][1][0],af[P][1][1],af[P][1][2],af[P][1][3], (aBase) + (uint32_t)(16*(LDAB)) + (s)*32); \
    ldsm4(bf[P][0][0],bf[P][0][1],bf[P][1][0],bf[P][1][1], (bBase) + (s)*32); \
    ldsm4(bf[P][2][0],bf[P][2][1],bf[P][3][0],bf[P][3][1], (bBase) + (uint32_t)(16*B_LDB) + (s)*32); \
    ldsm4(bf[P][4][0],bf[P][4][1],bf[P][5][0],bf[P][5][1], (bBase) + (uint32_t)(32*B_LDB) + (s)*32); \
    ldsm4(bf[P][6][0],bf[P][6][1],bf[P][7][0],bf[P][7][1], (bBase) + (uint32_t)(48*B_LDB) + (s)*32); \
  } while(0)

  // one 64-k chunk: 4 s-steps of k=16, fragment double-buffered
  #define CHUNK64(aBase, bBase, LDAB) do { \
    uint32_t af[2][2][4], bf[2][8][2]; \
    LDFRAG(0, aBase, bBase, LDAB, 0); \
    _Pragma("unroll") \
    for (int s=0;s<4;s++){ \
      if (s<3) LDFRAG((s+1)&1, aBase, bBase, LDAB, s+1); \
      _Pragma("unroll") \
      for (int mi=0;mi<2;mi++) \
        _Pragma("unroll") \
        for (int ni=0;ni<8;ni++) \
          mma16h(acc[mi][ni], af[s&1][mi], bf[s&1][ni]); \
    } } while(0)

  // ================= GEMM1: G = X @ WgT (4 chunks of k=64) =================
  LOAD_A64(0,0); LOAD_B64(g_WgTh,0,0); CP_COMMIT();
  CP_WAIT0(); __syncthreads();
  for (int kc=0;kc<4;kc++){
    if (kc<3){ LOAD_A64(kc+1,(kc+1)&1); LOAD_B64(g_WgTh,kc+1,(kc+1)&1); CP_COMMIT(); }
    {
      uint32_t aB = sbu + (uint32_t)(AOFF(kc&1) + wm*32*A_LDB) + offA144;
      uint32_t bB = sbu + (uint32_t)(BOFF(kc&1) + wn*64*B_LDB) + offB144;
      CHUNK64(aB, bB, A_LDB);
    }
    if (kc<3) CP_WAIT0();
    __syncthreads();
  }

  LOAD_B64(g_WoTh,0,0); CP_COMMIT();

  // ---- Epilogue 1: T = og * sigmoid(G + bg) -> fp16 into Ts ----
  #pragma unroll
  for (int mi=0;mi<2;mi++){
    #pragma unroll
    for (int ni=0;ni<8;ni++){
      const int col0 = wn*64 + ni*8 + lr*2;
      const int row0 = wm*32 + mi*16 + lq;
      const float bg0 = bgf[col0], bg1 = bgf[col0+1];
      const float o0  = ogf[col0], o1  = ogf[col0+1];
      float t00 = __fdividef(o0, 1.f+__expf(-(acc[mi][ni][0]+bg0)));
      float t01 = __fdividef(o1, 1.f+__expf(-(acc[mi][ni][1]+bg1)));
      float t10 = __fdividef(o0, 1.f+__expf(-(acc[mi][ni][2]+bg0)));
      float t11 = __fdividef(o1, 1.f+__expf(-(acc[mi][ni][3]+bg1)));
      *(__half2*)(smc + T_OFF + row0*T_LDB + col0*2)     = __floats2half2_rn(t00, t01);
      *(__half2*)(smc + T_OFF + (row0+8)*T_LDB + col0*2) = __floats2half2_rn(t10, t11);
      #pragma unroll
      for (int q=0;q<4;q++) acc[mi][ni][q]=0.f;
    }
  }
  CP_WAIT0();
  __syncthreads();

  // ================= GEMM2: out = T @ WoT (4 chunks of k=64) =================
  for (int kc=0;kc<4;kc++){
    if (kc<3){ LOAD_B64(g_WoTh,kc+1,(kc+1)&1); CP_COMMIT(); }
    {
      uint32_t aB = sbu + (uint32_t)(T_OFF + wm*32*T_LDB + kc*128) + offA528;
      uint32_t bB = sbu + (uint32_t)(BOFF(kc&1) + wn*64*B_LDB) + offB144;
      CHUNK64(aB, bB, T_LDB);
    }
    if (kc<3) CP_WAIT0();
    __syncthreads();
  }

  // ---- Epilogue 2: add bo, store (fp32) ----
  #pragma unroll
  for (int mi=0;mi<2;mi++){
    #pragma unroll
    for (int ni=0;ni<8;ni++){
      const int col0 = wn*64 + ni*8 + lr*2;
      const int row0 = wm*32 + mi*16 + lq;
      const float b0 = bof[col0], b1 = bof[col0+1];
      *(float2*)(out + (size_t)(r*SDIM + s0 + row0)*CDIM + col0) =
          make_float2(acc[mi][ni][0]+b0, acc[mi][ni][1]+b1);
      *(float2*)(out + (size_t)(r*SDIM + s0 + row0+8)*CDIM + col0) =
          make_float2(acc[mi][ni][2]+b0, acc[mi][ni][3]+b1);
    }
  }
  #undef LOAD_A64
  #undef LOAD_B64
  #undef LDFRAG
  #undef CHUNK64
}

// ---------------- launch ----------------
extern "C" void kernel_launch(void* const* d_in, const int* in_sizes, int n_in,
                              void* d_out, int out_size)
{
  const float* m    = (const float*)d_in[0];
  const float* mask = (const float*)d_in[1];
  const float* Wq   = (const float*)d_in[2];
  const float* Wk   = (const float*)d_in[3];
  const float* Wv   = (const float*)d_in[4];
  const float* Wg   = (const float*)d_in[5];
  const float* bg   = (const float*)d_in[6];
  const float* Wo   = (const float*)d_in[7];
  const float* bo   = (const float*)d_in[8];
  float* out = (float*)d_out;

  cudaFuncSetAttribute(ka_kv,  cudaFuncAttributeMaxDynamicSharedMemorySize, KA_SMEM);
  cudaFuncSetAttribute(kc_mma, cudaFuncAttributeMaxDynamicSharedMemorySize, KC_SMEM_BYTES);

  kprep <<<256, 256>>>(Wg, Wo, Wk, Wv);
  ka_kv <<<dim3(NTA, RDIM), 256, KA_SMEM>>>(m, mask);
  kb_attn<<<RDIM, 256>>>(mask, Wq);
  kc_mma<<<dim3(16, RDIM), 256, KC_SMEM_BYTES>>>(bg, bo, out);
}

// round 15
// speedup vs baseline: 1.1348x; 1.1348x over previous
#include <cuda_runtime.h>
#include <cuda_fp16.h>
#include <math.h>
#include <stdint.h>

#define RDIM 256
#define SDIM 1024
#define CDIM 256
#define NTA  8          // 128-token tiles per row (kernel A)

typedef unsigned long long ull;

// ---------------- device scratch ----------------
__device__ __half g_kvh[(size_t)RDIM*SDIM*64]; // per token: [0:32)=k, [32:64)=v (fp16)
__device__ float  g_qpool_part[RDIM*NTA*CDIM];
__device__ float  g_msum_part[RDIM*NTA];
__device__ float  g_gate[RDIM*CDIM];           // attention output o[r, h*32+c]
__device__ float  g_WkvT[64*CDIM];             // [Wk|Wv] transposed [n][k], tf32 RNA
__device__ __half g_WgTh[CDIM*CDIM];           // Wg transposed [n][k], fp16
__device__ __half g_WoTh[CDIM*CDIM];           // Wo transposed [n][k], fp16
__device__ __half g_mh[(size_t)RDIM*SDIM*CDIM];// fp16 copy of m (written by kA)

// ---------------- helpers ----------------
__device__ __forceinline__ uint32_t s2u(const void* p){
  uint32_t a;
  asm("{ .reg .u64 t; cvta.to.shared.u64 t, %1; cvt.u32.u64 %0, t; }" : "=r"(a) : "l"(p));
  return a;
}
__device__ __forceinline__ uint32_t tf32r(float x){
  uint32_t u; asm("cvt.rna.tf32.f32 %0, %1;" : "=r"(u) : "f"(x)); return u;
}
__device__ __forceinline__ void cpa16(uint32_t dst, const void* src){
  asm volatile("cp.async.cg.shared.global [%0], [%1], 16;" :: "r"(dst), "l"(src));
}
#define CP_COMMIT() asm volatile("cp.async.commit_group;" ::: "memory")
#define CP_WAIT0()  asm volatile("cp.async.wait_group 0;" ::: "memory")

__device__ __forceinline__ void mma8(float d[4], const uint32_t a[4], const uint32_t b[2]){
  asm volatile(
    "mma.sync.aligned.m16n8k8.row.col.f32.tf32.tf32.f32 "
    "{%0,%1,%2,%3}, {%4,%5,%6,%7}, {%8,%9}, {%0,%1,%2,%3};"
    : "+f"(d[0]), "+f"(d[1]), "+f"(d[2]), "+f"(d[3])
    : "r"(a[0]), "r"(a[1]), "r"(a[2]), "r"(a[3]), "r"(b[0]), "r"(b[1]));
}
__device__ __forceinline__ void mma16h(float d[4], const uint32_t a[4], const uint32_t b[2]){
  asm volatile(
    "mma.sync.aligned.m16n8k16.row.col.f32.f16.f16.f32 "
    "{%0,%1,%2,%3}, {%4,%5,%6,%7}, {%8,%9}, {%0,%1,%2,%3};"
    : "+f"(d[0]), "+f"(d[1]), "+f"(d[2]), "+f"(d[3])
    : "r"(a[0]), "r"(a[1]), "r"(a[2]), "r"(a[3]), "r"(b[0]), "r"(b[1]));
}
__device__ __forceinline__ void ldsm4(uint32_t &r0, uint32_t &r1, uint32_t &r2, uint32_t &r3,
                                      uint32_t addr){
  asm volatile("ldmatrix.sync.aligned.m8n8.x4.shared.b16 {%0,%1,%2,%3}, [%4];"
    : "=r"(r0), "=r"(r1), "=r"(r2), "=r"(r3) : "r"(addr));
}

// ---------------- Kernel P: transpose + round weights ----------------
__global__ void __launch_bounds__(256) kprep(const float* __restrict__ Wg,
                                             const float* __restrict__ Wo,
                                             const float* __restrict__ Wk,
                                             const float* __restrict__ Wv)
{
  const int n = blockIdx.x, k = threadIdx.x;
  g_WgTh[n*CDIM + k] = __float2half(Wg[k*CDIM + n]);
  g_WoTh[n*CDIM + k] = __float2half(Wo[k*CDIM + n]);
  if (n < 32)       g_WkvT[n*CDIM + k] = __uint_as_float(tf32r(Wk[k*32 + n]));
  else if (n < 64)  g_WkvT[n*CDIM + k] = __uint_as_float(tf32r(Wv[k*32 + (n-32)]));
}

// ---------------- Kernel A: k/v projection (tf32 mma + ldmatrix) + qpool + m->fp16 ----------------
#define KA_ALD   36
#define KA_ASZ   (128*KA_ALD)
#define KA_BOFF  (2*KA_ASZ)
#define KA_BLD   260
#define KA_MSK   (KA_BOFF + 64*KA_BLD)
#define KA_SMEM  ((KA_MSK + 128)*4)    // 103936 B

union H2U4 { uint4 v; __half2 h[4]; };

__global__ void __launch_bounds__(256,2) ka_kv(const float* __restrict__ m,
                                               const float* __restrict__ mask)
{
  extern __shared__ float sm[];
  const uint32_t sbu = s2u(sm);
  const int t = threadIdx.x, lane = t&31, w = t>>5;
  const int wm = w>>1, wn = w&1;
  const int lq = lane>>2, lr = lane&3;
  const int til = lane>>3, rw = lane&7;
  const int r = blockIdx.y, tile = blockIdx.x, s0 = tile*128;

  const float4* m4 = (const float4*)(m + (size_t)(r*SDIM + s0)*CDIM);
  const float4* B4 = (const float4*)g_WkvT;

  const uint32_t offA36  = (uint32_t)((((til&1)*8 + rw)*KA_ALD)*4 + (til>>1)*16);
  const uint32_t offB260 = (uint32_t)((((til>>1)*8 + rw)*KA_BLD)*4 + (til&1)*16);

  if (t < 128) sm[KA_MSK + t] = mask[r*SDIM + s0 + t];

  #pragma unroll
  for (int i=0;i<16;i++){
    int f = i*256 + t; int n = f>>6, q = f&63;
    cpa16(sbu + (uint32_t)(KA_BOFF + n*KA_BLD + q*4)*4, B4 + n*64 + q);
  }
  #pragma unroll
  for (int i=0;i<4;i++){
    int f = i*256 + t; int row = f>>3, q = f&7;
    cpa16(sbu + (uint32_t)(0*KA_ASZ + row*KA_ALD + q*4)*4, m4 + row*64 + 0*8 + q);
  }
  CP_COMMIT(); CP_WAIT0();
  __syncthreads();

  if (t < 32){
    float s = sm[KA_MSK+t] + sm[KA_MSK+t+32] + sm[KA_MSK+t+64] + sm[KA_MSK+t+96];
    #pragma unroll
    for (int o=16;o;o>>=1) s += __shfl_xor_sync(0xffffffffu, s, o);
    if (t==0) g_msum_part[r*NTA + tile] = s;
  }

  float acc[2][4][4];
  #pragma unroll
  for (int mi=0;mi<2;mi++)
    #pragma unroll
    for (int ni=0;ni<4;ni++)
      #pragma unroll
      for (int q=0;q<4;q++) acc[mi][ni][q]=0.f;

  const int qch = t>>3, qsub = t&7;

  for (int kc=0;kc<8;kc++){
    if (kc<7){
      #pragma unroll
      for (int i=0;i<4;i++){
        int f = i*256 + t; int row = f>>3, q = f&7;
        cpa16(sbu + (uint32_t)(((kc+1)&1)*KA_ASZ + row*KA_ALD + q*4)*4,
              m4 + row*64 + (kc+1)*8 + q);
      }
      CP_COMMIT();
    }
    const float* As = sm + (kc&1)*KA_ASZ;
    const uint32_t aBase = sbu + (uint32_t)(((kc&1)*KA_ASZ + wm*32*KA_ALD)*4) + offA36;
    const uint32_t bBase = sbu + (uint32_t)((KA_BOFF + wn*32*KA_BLD + kc*32)*4) + offB260;
    #pragma unroll
    for (int s=0;s<4;s++){
      uint32_t a[2][4], b[4][2];
      ldsm4(a[0][0],a[0][1],a[0][2],a[0][3], aBase + s*32);
      ldsm4(a[1][0],a[1][1],a[1][2],a[1][3], aBase + (uint32_t)(16*KA_ALD*4) + s*32);
      ldsm4(b[0][0],b[0][1],b[1][0],b[1][1], bBase + s*32);
      ldsm4(b[2][0],b[2][1],b[3][0],b[3][1], bBase + (uint32_t)(16*KA_BLD*4) + s*32);
      #pragma unroll
      for (int mi=0;mi<2;mi++)
        #pragma unroll
        for (int ni=0;ni<4;ni++)
          mma8(acc[mi][ni], a[mi], b[ni]);
    }
    // fused qpool partial (exact fp32)
    {
      float qa = 0.f;
      #pragma unroll
      for (int j=0;j<16;j++){
        int row = qsub + 8*j;
        qa += As[row*KA_ALD + qch] * sm[KA_MSK + row];
      }
      qa += __shfl_xor_sync(0xffffffffu, qa, 4);
      qa += __shfl_xor_sync(0xffffffffu, qa, 2);
      qa += __shfl_xor_sync(0xffffffffu, qa, 1);
      if (qsub==0) g_qpool_part[(r*NTA + tile)*CDIM + kc*32 + qch] = qa;
    }
    // fp16 m copy
    {
      int row = t>>1, seg = t&1;
      const float* src = As + row*KA_ALD + seg*16;
      H2U4 u0, u1;
      #pragma unroll
      for (int j=0;j<4;j++) u0.h[j] = __floats2half2_rn(src[2*j],   src[2*j+1]);
      #pragma unroll
      for (int j=0;j<4;j++) u1.h[j] = __floats2half2_rn(src[8+2*j], src[8+2*j+1]);
      __half* dst = g_mh + (size_t)(r*SDIM + s0 + row)*CDIM + kc*32 + seg*16;
      *(uint4*)dst       = u0.v;
      *((uint4*)dst + 1) = u1.v;
    }
    if (kc<7) CP_WAIT0();
    __syncthreads();
  }

  // store k/v (fp16)
  #pragma unroll
  for (int mi=0;mi<2;mi++){
    #pragma unroll
    for (int ni=0;ni<4;ni++){
      const int col0 = wn*32 + ni*8 + lr*2;
      const int row0 = wm*32 + mi*16 + lq;
      *(__half2*)(g_kvh + (size_t)(r*SDIM + s0 + row0)*64 + col0) =
          __floats2half2_rn(acc[mi][ni][0], acc[mi][ni][1]);
      *(__half2*)(g_kvh + (size_t)(r*SDIM + s0 + row0+8)*64 + col0) =
          __floats2half2_rn(acc[mi][ni][2], acc[mi][ni][3]);
    }
  }
}

// ---------------- Kernel B: q, logits, softmax, o (fp32 math, fp16 k/v) ----------------
__global__ void __launch_bounds__(256) kb_attn(const float* __restrict__ mask,
                                               const float* __restrict__ Wq)
{
  __shared__ float qp[256];
  __shared__ float qh[256];
  __shared__ float lg[8*1024];
  __shared__ float vs[128*36];
  __shared__ float msum_s;
  const int t = threadIdx.x, r = blockIdx.x;

  float qa = 0.f;
  #pragma unroll
  for (int i=0;i<NTA;i++) qa += g_qpool_part[(r*NTA+i)*CDIM + t];
  if (t==0){
    float s=0.f;
    #pragma unroll
    for (int i=0;i<NTA;i++) s += g_msum_part[r*NTA+i];
    msum_s = s;
  }
  __syncthreads();
  qp[t] = qa / (msum_s + 1e-10f);
  __syncthreads();

  float qv = 0.f;
  for (int c=0;c<CDIM;c++) qv += qp[c]*Wq[c*256+t];
  qh[t] = qv * 0.17677669529663687f;
  __syncthreads();

  for (int it=0; it<4; it++){
    int s = it*256 + t;
    float kreg[32];
    const uint4* kv = (const uint4*)(g_kvh + (size_t)(r*SDIM+s)*64);
    #pragma unroll
    for (int qq=0;qq<4;qq++){
      H2U4 u; u.v = kv[qq];
      #pragma unroll
      for (int j=0;j<4;j++){
        float2 f2 = __half22float2(u.h[j]);
        kreg[qq*8+2*j]   = f2.x;
        kreg[qq*8+2*j+1] = f2.y;
      }
    }
    float bias = 1.0e9f*(mask[r*SDIM+s]-1.0f);
    #pragma unroll
    for (int h=0;h<8;h++){
      float d=0.f;
      #pragma unroll
      for (int q=0;q<32;q++) d += qh[h*32+q]*kreg[q];
      lg[h*1024+s] = d + bias;
    }
  }
  __syncthreads();

  const int w = t>>5, lane = t&31;
  {
    float mx = -3.4e38f;
    for (int s=lane; s<1024; s+=32) mx = fmaxf(mx, lg[w*1024+s]);
    #pragma unroll
    for (int o=16;o;o>>=1) mx = fmaxf(mx, __shfl_xor_sync(0xffffffffu, mx, o));
    float sum = 0.f;
    for (int s=lane; s<1024; s+=32){
      float e = __expf(lg[w*1024+s]-mx);
      lg[w*1024+s] = e; sum += e;
    }
    #pragma unroll
    for (int o=16;o;o>>=1) sum += __shfl_xor_sync(0xffffffffu, sum, o);
    float inv = 1.0f/sum;
    for (int s=lane; s<1024; s+=32) lg[w*1024+s] *= inv;
  }
  __syncthreads();

  float acc = 0.f;
  for (int tile=0;tile<8;tile++){
    {
      int tk = t>>1, seg = t&1;
      const uint4* src = (const uint4*)(g_kvh + (size_t)(r*SDIM+tile*128+tk)*64 + 32 + seg*16);
      H2U4 u0, u1; u0.v = src[0]; u1.v = src[1];
      float* d = vs + tk*36 + seg*16;
      #pragma unroll
      for (int j=0;j<4;j++){
        float2 f2 = __half22float2(u0.h[j]);
        d[2*j] = f2.x; d[2*j+1] = f2.y;
      }
      #pragma unroll
      for (int j=0;j<4;j++){
        float2 f2 = __half22float2(u1.h[j]);
        d[8+2*j] = f2.x; d[8+2*j+1] = f2.y;
      }
    }
    __syncthreads();
    #pragma unroll 8
    for (int tk=0;tk<128;tk++) acc += lg[w*1024 + tile*128+tk] * vs[tk*36 + lane];
    __syncthreads();
  }
  g_gate[r*CDIM + t] = acc;
}

// ---------------- Kernel C: out = (sigmoid(m@Wg+bg)*o) @ Wo + bo  (fp16 mma m16n8k16) ----------------
// R12 configuration (measured kc optimum 248.6us): 512 threads = 16 warps (4x4),
// warp tile 32x64, CTA tile 128x256, K chunks of 64, A+B double-buffered, T fp16 resident.
#define A_LDB   144                   // A chunk row stride bytes (64 halves + 16B pad)
#define A_SZB   (128*A_LDB)           // 18432
#define B_LDB   144
#define B_SZB   (256*B_LDB)           // 36864
#define AOFF(b) ((b)*A_SZB)
#define BOFF(b) (2*A_SZB + (b)*B_SZB)
#define T_OFF   (2*A_SZB + 2*B_SZB)   // 110592
#define T_LDB   528                   // 256 halves + pad (bytes)
#define OGB     (T_OFF + 128*T_LDB)   // 178176
#define BGB     (OGB + 1024)
#define BOB     (BGB + 1024)
#define KC_SMEM_BYTES (BOB + 1024)    // 181248

__global__ void __launch_bounds__(512,1) kc_mma(const float* __restrict__ bgp,
    const float* __restrict__ bop, float* __restrict__ out)
{
  extern __shared__ char smc[];
  const uint32_t sbu = s2u(smc);
  float* ogf = (float*)(smc + OGB);
  float* bgf = (float*)(smc + BGB);
  float* bof = (float*)(smc + BOB);
  const int t = threadIdx.x, lane = t&31, w = t>>5;
  const int wm = w>>2, wn = w&3;
  const int lq = lane>>2, lr = lane&3;
  const int til = lane>>3, rw = lane&7;
  const int r = blockIdx.y, tile = blockIdx.x, s0 = tile*128;

  if (t < 256){
    ogf[t] = g_gate[r*CDIM+t];
    bgf[t] = bgp[t];
    bof[t] = bop[t];
  }

  const __half* mh = g_mh + (size_t)(r*SDIM + s0)*CDIM;

  const uint32_t offA144 = (uint32_t)(((til&1)*8 + rw)*A_LDB + (til>>1)*16);
  const uint32_t offA528 = (uint32_t)(((til&1)*8 + rw)*T_LDB + (til>>1)*16);
  const uint32_t offB144 = (uint32_t)(((til>>1)*8 + rw)*B_LDB + (til&1)*16);

  float acc[2][8][4];
  #pragma unroll
  for (int mi=0;mi<2;mi++)
    #pragma unroll
    for (int ni=0;ni<8;ni++)
      #pragma unroll
      for (int q=0;q<4;q++) acc[mi][ni][q]=0.f;

  // A chunk: 128 rows x 64 halves = 1024 x 16B, 2 per thread
  #define LOAD_A64(kc, b) do { \
    _Pragma("unroll") \
    for (int i=0;i<2;i++){ \
      int f=i*512+t; int row=f>>3, q=f&7; \
      cpa16(sbu + (uint32_t)(AOFF(b) + row*A_LDB + q*16), \
            mh + (size_t)row*CDIM + (kc)*64 + q*8); \
    } } while(0)
  // B chunk: 256 n x 64 halves = 2048 x 16B, 4 per thread
  #define LOAD_B64(Wh, kc, b) do { \
    _Pragma("unroll") \
    for (int i=0;i<4;i++){ \
      int f=i*512+t; int n=f>>3, q=f&7; \
      cpa16(sbu + (uint32_t)(BOFF(b) + n*B_LDB + q*16), \
            (Wh) + (size_t)n*CDIM + (kc)*64 + q*8); \
    } } while(0)

  // one 64-k chunk: 4 s-steps of k=16
  #define CHUNK64(aBase, bBase, LDAB) do { \
    _Pragma("unroll") \
    for (int s=0;s<4;s++){ \
      uint32_t a[2][4], b[8][2]; \
      ldsm4(a[0][0],a[0][1],a[0][2],a[0][3], (aBase) + s*32); \
      ldsm4(a[1][0],a[1][1],a[1][2],a[1][3], (aBase) + (uint32_t)(16*(LDAB)) + s*32); \
      ldsm4(b[0][0],b[0][1],b[1][0],b[1][1], (bBase) + s*32); \
      ldsm4(b[2][0],b[2][1],b[3][0],b[3][1], (bBase) + (uint32_t)(16*B_LDB) + s*32); \
      ldsm4(b[4][0],b[4][1],b[5][0],b[5][1], (bBase) + (uint32_t)(32*B_LDB) + s*32); \
      ldsm4(b[6][0],b[6][1],b[7][0],b[7][1], (bBase) + (uint32_t)(48*B_LDB) + s*32); \
      _Pragma("unroll") \
      for (int mi=0;mi<2;mi++) \
        _Pragma("unroll") \
        for (int ni=0;ni<8;ni++) \
          mma16h(acc[mi][ni], a[mi], b[ni]); \
    } } while(0)

  // ================= GEMM1: G = X @ WgT (4 chunks of k=64) =================
  LOAD_A64(0,0); LOAD_B64(g_WgTh,0,0); CP_COMMIT();
  CP_WAIT0(); __syncthreads();
  for (int kc=0;kc<4;kc++){
    if (kc<3){ LOAD_A64(kc+1,(kc+1)&1); LOAD_B64(g_WgTh,kc+1,(kc+1)&1); CP_COMMIT(); }
    {
      uint32_t aB = sbu + (uint32_t)(AOFF(kc&1) + wm*32*A_LDB) + offA144;
      uint32_t bB = sbu + (uint32_t)(BOFF(kc&1) + wn*64*B_LDB) + offB144;
      CHUNK64(aB, bB, A_LDB);
    }
    if (kc<3) CP_WAIT0();
    __syncthreads();
  }

  LOAD_B64(g_WoTh,0,0); CP_COMMIT();

  // ---- Epilogue 1: T = og * sigmoid(G + bg) -> fp16 into Ts ----
  #pragma unroll
  for (int mi=0;mi<2;mi++){
    #pragma unroll
    for (int ni=0;ni<8;ni++){
      const int col0 = wn*64 + ni*8 + lr*2;
      const int row0 = wm*32 + mi*16 + lq;
      const float bg0 = bgf[col0], bg1 = bgf[col0+1];
      const float o0  = ogf[col0], o1  = ogf[col0+1];
      float t00 = __fdividef(o0, 1.f+__expf(-(acc[mi][ni][0]+bg0)));
      float t01 = __fdividef(o1, 1.f+__expf(-(acc[mi][ni][1]+bg1)));
      float t10 = __fdividef(o0, 1.f+__expf(-(acc[mi][ni][2]+bg0)));
      float t11 = __fdividef(o1, 1.f+__expf(-(acc[mi][ni][3]+bg1)));
      *(__half2*)(smc + T_OFF + row0*T_LDB + col0*2)     = __floats2half2_rn(t00, t01);
      *(__half2*)(smc + T_OFF + (row0+8)*T_LDB + col0*2) = __floats2half2_rn(t10, t11);
      #pragma unroll
      for (int q=0;q<4;q++) acc[mi][ni][q]=0.f;
    }
  }
  CP_WAIT0();
  __syncthreads();

  // ================= GEMM2: out = T @ WoT (4 chunks of k=64) =================
  for (int kc=0;kc<4;kc++){
    if (kc<3){ LOAD_B64(g_WoTh,kc+1,(kc+1)&1); CP_COMMIT(); }
    {
      uint32_t aB = sbu + (uint32_t)(T_OFF + wm*32*T_LDB + kc*128) + offA528;
      uint32_t bB = sbu + (uint32_t)(BOFF(kc&1) + wn*64*B_LDB) + offB144;
      CHUNK64(aB, bB, T_LDB);
    }
    if (kc<3) CP_WAIT0();
    __syncthreads();
  }

  // ---- Epilogue 2: add bo, store (fp32) ----
  #pragma unroll
  for (int mi=0;mi<2;mi++){
    #pragma unroll
    for (int ni=0;ni<8;ni++){
      const int col0 = wn*64 + ni*8 + lr*2;
      const int row0 = wm*32 + mi*16 + lq;
      const float b0 = bof[col0], b1 = bof[col0+1];
      *(float2*)(out + (size_t)(r*SDIM + s0 + row0)*CDIM + col0) =
          make_float2(acc[mi][ni][0]+b0, acc[mi][ni][1]+b1);
      *(float2*)(out + (size_t)(r*SDIM + s0 + row0+8)*CDIM + col0) =
          make_float2(acc[mi][ni][2]+b0, acc[mi][ni][3]+b1);
    }
  }
  #undef LOAD_A64
  #undef LOAD_B64
  #undef CHUNK64
}

// ---------------- launch ----------------
extern "C" void kernel_launch(void* const* d_in, const int* in_sizes, int n_in,
                              void* d_out, int out_size)
{
  const float* m    = (const float*)d_in[0];
  const float* mask = (const float*)d_in[1];
  const float* Wq   = (const float*)d_in[2];
  const float* Wk   = (const float*)d_in[3];
  const float* Wv   = (const float*)d_in[4];
  const float* Wg   = (const float*)d_in[5];
  const float* bg   = (const float*)d_in[6];
  const float* Wo   = (const float*)d_in[7];
  const float* bo   = (const float*)d_in[8];
  float* out = (float*)d_out;

  cudaFuncSetAttribute(ka_kv,  cudaFuncAttributeMaxDynamicSharedMemorySize, KA_SMEM);
  cudaFuncSetAttribute(kc_mma, cudaFuncAttributeMaxDynamicSharedMemorySize, KC_SMEM_BYTES);

  kprep <<<256, 256>>>(Wg, Wo, Wk, Wv);
  ka_kv <<<dim3(NTA, RDIM), 256, KA_SMEM>>>(m, mask);
  kb_attn<<<RDIM, 256>>>(mask, Wq);
  kc_mma<<<dim3(8, RDIM), 512, KC_SMEM_BYTES>>>(bg, bo, out);
}